// round 1
// baseline (speedup 1.0000x reference)
#include <cuda_runtime.h>
#include <cuda_bf16.h>

#define EPS 1e-7f

// Global scratch (no allocations allowed).
__device__ double g_mse_sum;
__device__ double g_iou_sum;
__device__ unsigned long long g_n_inc;
__device__ unsigned long long g_n_corr;

__global__ void zero_scratch_kernel() {
    g_mse_sum = 0.0;
    g_iou_sum = 0.0;
    g_n_inc = 0ULL;
    g_n_corr = 0ULL;
}

template <int BLOCK>
__global__ void iou_dots_reduce_kernel(const float4* __restrict__ pr,
                                       const float4* __restrict__ gt,
                                       int n) {
    float mse_acc = 0.0f;
    float iou_acc = 0.0f;
    int inc_acc = 0;
    int corr_acc = 0;

    int stride = gridDim.x * BLOCK;
    for (int i = blockIdx.x * BLOCK + threadIdx.x; i < n; i += stride) {
        float4 p = pr[i];   // (cx, cy, w, h)
        float4 g = gt[i];

        // gt corners
        float x_min_t = g.x - g.z * 0.5f;
        float x_max_t = g.x + g.z * 0.5f;
        float y_min_t = g.y - g.w * 0.5f;
        float y_max_t = g.y + g.w * 0.5f;
        // pred corners, clipped to [0,1]
        float x_min_p = fmaxf(p.x - p.z * 0.5f, 0.0f);
        float x_max_p = fminf(p.x + p.z * 0.5f, 1.0f);
        float y_min_p = fmaxf(p.y - p.w * 0.5f, 0.0f);
        float y_max_p = fminf(p.y + p.w * 0.5f, 1.0f);
        // overlap box
        float o0 = fmaxf(x_min_t, x_min_p);
        float o1 = fmaxf(y_min_t, y_min_p);
        float o2 = fminf(x_max_t, x_max_p);
        float o3 = fminf(y_max_t, y_max_p);

        bool incorrect = (o2 < o0) || (o3 < o1);

        if (incorrect) {
            float dx = p.x - g.x;
            float dy = p.y - g.y;
            float dz = p.z - g.z;
            float dw = p.w - g.w;
            mse_acc += dx * dx + dy * dy + dz * dz + dw * dw;
            inc_acc += 1;
        } else {
            float area_p = p.z * p.w;
            float area_g = g.z * g.w;
            float inter = (o2 - o0) * (o3 - o1);
            float iou = inter / (area_p + area_g - inter + EPS);
            iou_acc += iou;
            corr_acc += 1;
        }
    }

    // Warp reduce (fp32 within warp; cast up to double at block level)
    #pragma unroll
    for (int off = 16; off > 0; off >>= 1) {
        mse_acc += __shfl_down_sync(0xFFFFFFFFu, mse_acc, off);
        iou_acc += __shfl_down_sync(0xFFFFFFFFu, iou_acc, off);
        inc_acc += __shfl_down_sync(0xFFFFFFFFu, inc_acc, off);
        corr_acc += __shfl_down_sync(0xFFFFFFFFu, corr_acc, off);
    }

    __shared__ double s_mse[BLOCK / 32];
    __shared__ double s_iou[BLOCK / 32];
    __shared__ int s_inc[BLOCK / 32];
    __shared__ int s_corr[BLOCK / 32];

    int lane = threadIdx.x & 31;
    int wid = threadIdx.x >> 5;
    if (lane == 0) {
        s_mse[wid] = (double)mse_acc;
        s_iou[wid] = (double)iou_acc;
        s_inc[wid] = inc_acc;
        s_corr[wid] = corr_acc;
    }
    __syncthreads();

    if (wid == 0) {
        constexpr int NW = BLOCK / 32;
        double m = (lane < NW) ? s_mse[lane] : 0.0;
        double u = (lane < NW) ? s_iou[lane] : 0.0;
        int ni = (lane < NW) ? s_inc[lane] : 0;
        int nc = (lane < NW) ? s_corr[lane] : 0;
        #pragma unroll
        for (int off = 16; off > 0; off >>= 1) {
            m += __shfl_down_sync(0xFFFFFFFFu, m, off);
            u += __shfl_down_sync(0xFFFFFFFFu, u, off);
            ni += __shfl_down_sync(0xFFFFFFFFu, ni, off);
            nc += __shfl_down_sync(0xFFFFFFFFu, nc, off);
        }
        if (lane == 0) {
            atomicAdd(&g_mse_sum, m);
            atomicAdd(&g_iou_sum, u);
            atomicAdd(&g_n_inc, (unsigned long long)ni);
            atomicAdd(&g_n_corr, (unsigned long long)nc);
        }
    }
}

__global__ void finalize_kernel(float* __restrict__ out) {
    double mse_sum = g_mse_sum;
    double iou_sum = g_iou_sum;
    unsigned long long n_inc = g_n_inc;
    unsigned long long n_corr = g_n_corr;

    double denom_mse = (double)((n_inc * 4ULL > 0ULL) ? n_inc * 4ULL : 1ULL);
    double mse_mean = mse_sum / denom_mse;
    double denom_iou = (double)((n_corr > 0ULL) ? n_corr : 1ULL);
    double iou_mean = iou_sum / denom_iou;

    double res;
    if (n_corr > 0ULL) {
        res = iou_mean + ((n_inc > 0ULL) ? -mse_mean : 0.0);
    } else {
        res = -mse_mean;
    }
    out[0] = (float)res;
}

extern "C" void kernel_launch(void* const* d_in, const int* in_sizes, int n_in,
                              void* d_out, int out_size) {
    const float4* pr = (const float4*)d_in[0];
    const float4* gt = (const float4*)d_in[1];
    float* out = (float*)d_out;
    int n = in_sizes[0] / 4;  // element count -> box count

    constexpr int BLOCK = 256;
    int blocks = 148 * 8;  // ~1184 blocks, grid-stride

    zero_scratch_kernel<<<1, 1>>>();
    iou_dots_reduce_kernel<BLOCK><<<blocks, BLOCK>>>(pr, gt, n);
    finalize_kernel<<<1, 1>>>(out);
}